// round 8
// baseline (speedup 1.0000x reference)
#include <cuda_runtime.h>
#include <cuda_bf16.h>
#include <cstdint>

#define NN      8192
#define NODE    256
#define DEG     16
#define NFEAT   128
#define NHID    256
#define NCLASS  64

// ---------------- device scratch (no allocation allowed) --------------------
__device__ float g_xT [NFEAT * NN];       // x^T   [128][8192]
__device__ float g_W1t[NHID * NFEAT];     // W1^T  [256][128]
__device__ float g_W2t[NCLASS * NHID];    // W2^T  [64][256]
__device__ float g_X  [NN * NFEAT];       // adj @ x
__device__ float g_H  [NN * NHID];        // relu(gX @ W1)
__device__ float g_Tt [NCLASS * NN];      // (gH @ W2)^T  [64][8192]

__device__ __forceinline__ uint32_t f2tf32(float a) {
    uint32_t u; asm("cvt.rna.tf32.f32 %0, %1;" : "=r"(u) : "f"(a)); return u;
}
__device__ __forceinline__ void mma_tf32(float c[4], const uint32_t a[4], const uint32_t b[2]) {
    asm volatile(
        "mma.sync.aligned.m16n8k8.row.col.f32.tf32.tf32.f32 "
        "{%0,%1,%2,%3}, {%4,%5,%6,%7}, {%8,%9}, {%0,%1,%2,%3};"
        : "+f"(c[0]), "+f"(c[1]), "+f"(c[2]), "+f"(c[3])
        : "r"(a[0]), "r"(a[1]), "r"(a[2]), "r"(a[3]), "r"(b[0]), "r"(b[1]));
}

// ---------------------------------------------------------------------------
// K0: 32x32 tile transposes: x -> xT, W1 -> W1t, W2 -> W2t.
// ---------------------------------------------------------------------------
__global__ __launch_bounds__(256)
void transpose_kernel(const float* __restrict__ x, const float* __restrict__ W1,
                      const float* __restrict__ W2, float* __restrict__ xT,
                      float* __restrict__ W1t, float* __restrict__ W2t)
{
    const float* src; float* dst; int R, C, tr, tc;
    int bid = blockIdx.x;
    if (bid < 1024)      { src = x;  dst = xT;  R = NN;   C = NFEAT;  tr = bid >> 2;  tc = bid & 3; }
    else if (bid < 1056) { int b = bid - 1024; src = W1; dst = W1t; R = NFEAT; C = NHID;  tr = b >> 3; tc = b & 7; }
    else                 { int b = bid - 1056; src = W2; dst = W2t; R = NHID;  C = NCLASS; tr = b >> 1; tc = b & 1; }

    __shared__ float t[32][33];
    const int r  = threadIdx.x >> 3;   // 0..31
    const int fq = threadIdx.x & 7;    // 0..7
    float4 v = *reinterpret_cast<const float4*>(src + (size_t)(tr * 32 + r) * C + tc * 32 + fq * 4);
    t[r][fq * 4 + 0] = v.x; t[r][fq * 4 + 1] = v.y;
    t[r][fq * 4 + 2] = v.z; t[r][fq * 4 + 3] = v.w;
    __syncthreads();
    float4 o;
    o.x = t[fq * 4 + 0][r]; o.y = t[fq * 4 + 1][r];
    o.z = t[fq * 4 + 2][r]; o.w = t[fq * 4 + 3][r];
    *reinterpret_cast<float4*>(dst + (size_t)(tc * 32 + r) * R + tr * 32 + fq * 4) = o;
}

// ---------------------------------------------------------------------------
// agg_mma: C[BM rows] = adj_block @ B, adjacency synthesized from per-row
// 256-bit bitmaps (A-fragments built in registers, exact 1.0 tf32).
// Bt: [BN][8192] row-major (k = global node, contiguous). 2-term tf32 (B hi/lo).
// If LSM: fused log_softmax epilogue (warp tile must cover full row: WN == BN).
// ---------------------------------------------------------------------------
template<int BM, int BN, int WN, bool LSM>
__global__ __launch_bounds__(256)
void agg_mma(const float* __restrict__ Bt, const int* __restrict__ edge,
             float* __restrict__ C, int ldc)
{
    constexpr int LDS_   = 36;
    constexpr int NWN    = BN / WN;
    constexpr int WM     = BM / (8 / NWN);
    constexpr int MSUB   = WM / 16;
    constexpr int NSUB   = WN / 8;
    constexpr int NCHUNK = 8;                 // K = 256
    constexpr int B_FLT  = BN * LDS_;
    constexpr int STAGE_FLT = 2 * B_FLT;
    constexpr int BPT    = BN * 8 / 256;

    extern __shared__ float sm[];
    __shared__ unsigned bm[BM][8];

    const int tid   = threadIdx.x;
    const int wid   = tid >> 5;
    const int lane  = tid & 31;
    const int brow  = blockIdx.x * BM;
    const int blk   = brow >> 8;
    const int warpM = (wid / NWN) * WM;
    const int warpN = (wid % NWN) * WN;
    const int grp   = lane >> 2;
    const int qk    = lane & 3;

    // Build adjacency bitmaps for this CTA's BM rows (dedup + -1 skip for free).
    if (tid < BM) {
        #pragma unroll
        for (int w = 0; w < 8; ++w) bm[tid][w] = 0u;
        const int4* ep = reinterpret_cast<const int4*>(edge + (size_t)(brow + tid) * DEG);
        #pragma unroll
        for (int w = 0; w < 4; ++w) {
            int4 e4 = ep[w];
            if (e4.x >= 0) bm[tid][e4.x >> 5] |= 1u << (e4.x & 31);
            if (e4.y >= 0) bm[tid][e4.y >> 5] |= 1u << (e4.y & 31);
            if (e4.z >= 0) bm[tid][e4.z >> 5] |= 1u << (e4.z & 31);
            if (e4.w >= 0) bm[tid][e4.w >> 5] |= 1u << (e4.w & 31);
        }
    }

    float acc[MSUB][NSUB][4] = {};
    float4 pb[BPT];
    const float* Bbase = Bt + (size_t)blk * NODE;

    #pragma unroll
    for (int j = 0; j < BPT; ++j) {
        int i = tid + j * 256;
        pb[j] = *reinterpret_cast<const float4*>(
            Bbase + (size_t)(i >> 3) * NN + ((i & 7) << 2));
    }

    for (int c = 0; c < NCHUNK; ++c) {
        float* Bh = sm + (c & 1) * STAGE_FLT;
        float* Bl = Bh + B_FLT;
        #pragma unroll
        for (int j = 0; j < BPT; ++j) {
            int i = tid + j * 256;
            int r = i >> 3, f = (i & 7) << 2;
            float4 v = pb[j];
            float* ph = Bh + r * LDS_ + f;
            float* pl = Bl + r * LDS_ + f;
            float hx = __uint_as_float(f2tf32(v.x));
            float hy = __uint_as_float(f2tf32(v.y));
            float hz = __uint_as_float(f2tf32(v.z));
            float hw = __uint_as_float(f2tf32(v.w));
            ph[0] = hx; ph[1] = hy; ph[2] = hz; ph[3] = hw;
            pl[0] = __uint_as_float(f2tf32(v.x - hx));
            pl[1] = __uint_as_float(f2tf32(v.y - hy));
            pl[2] = __uint_as_float(f2tf32(v.z - hz));
            pl[3] = __uint_as_float(f2tf32(v.w - hw));
        }
        if (c + 1 < NCHUNK) {
            #pragma unroll
            for (int j = 0; j < BPT; ++j) {
                int i = tid + j * 256;
                pb[j] = *reinterpret_cast<const float4*>(
                    Bbase + (size_t)(i >> 3) * NN + (c + 1) * 32 + ((i & 7) << 2));
            }
        }
        __syncthreads();

        unsigned bw0[MSUB], bw1[MSUB];
        #pragma unroll
        for (int ms = 0; ms < MSUB; ++ms) {
            bw0[ms] = bm[warpM + ms * 16 + grp][c];
            bw1[ms] = bm[warpM + ms * 16 + 8 + grp][c];
        }
        #pragma unroll
        for (int ks = 0; ks < 4; ++ks) {
            const int kb = ks * 8;
            uint32_t af[MSUB][4];
            #pragma unroll
            for (int ms = 0; ms < MSUB; ++ms) {
                af[ms][0] = ((bw0[ms] >> (kb + qk)) & 1u)     ? 0x3f800000u : 0u;
                af[ms][1] = ((bw1[ms] >> (kb + qk)) & 1u)     ? 0x3f800000u : 0u;
                af[ms][2] = ((bw0[ms] >> (kb + qk + 4)) & 1u) ? 0x3f800000u : 0u;
                af[ms][3] = ((bw1[ms] >> (kb + qk + 4)) & 1u) ? 0x3f800000u : 0u;
            }
            uint32_t bfh[NSUB][2], bfl[NSUB][2];
            #pragma unroll
            for (int ns = 0; ns < NSUB; ++ns) {
                int b0 = (warpN + ns * 8 + grp) * LDS_ + kb + qk;
                bfh[ns][0] = __float_as_uint(Bh[b0]);
                bfh[ns][1] = __float_as_uint(Bh[b0 + 4]);
                bfl[ns][0] = __float_as_uint(Bl[b0]);
                bfl[ns][1] = __float_as_uint(Bl[b0 + 4]);
            }
            #pragma unroll
            for (int ms = 0; ms < MSUB; ++ms)
                #pragma unroll
                for (int ns = 0; ns < NSUB; ++ns) {
                    mma_tf32(acc[ms][ns], af[ms], bfh[ns]);
                    mma_tf32(acc[ms][ns], af[ms], bfl[ns]);
                }
        }
    }

    if (LSM) {
        // warp tile 16 x BN (MSUB==1, warpN==0): rows grp and grp+8.
        float m0 = -1e30f, m1 = -1e30f;
        #pragma unroll
        for (int ns = 0; ns < NSUB; ++ns) {
            m0 = fmaxf(m0, fmaxf(acc[0][ns][0], acc[0][ns][1]));
            m1 = fmaxf(m1, fmaxf(acc[0][ns][2], acc[0][ns][3]));
        }
        m0 = fmaxf(m0, __shfl_xor_sync(0xffffffffu, m0, 1));
        m0 = fmaxf(m0, __shfl_xor_sync(0xffffffffu, m0, 2));
        m1 = fmaxf(m1, __shfl_xor_sync(0xffffffffu, m1, 1));
        m1 = fmaxf(m1, __shfl_xor_sync(0xffffffffu, m1, 2));
        float s0 = 0.f, s1 = 0.f;
        #pragma unroll
        for (int ns = 0; ns < NSUB; ++ns) {
            s0 += expf(acc[0][ns][0] - m0) + expf(acc[0][ns][1] - m0);
            s1 += expf(acc[0][ns][2] - m1) + expf(acc[0][ns][3] - m1);
        }
        s0 += __shfl_xor_sync(0xffffffffu, s0, 1);
        s0 += __shfl_xor_sync(0xffffffffu, s0, 2);
        s1 += __shfl_xor_sync(0xffffffffu, s1, 1);
        s1 += __shfl_xor_sync(0xffffffffu, s1, 2);
        float lse0 = logf(s0) + m0;
        float lse1 = logf(s1) + m1;
        const int r0 = brow + warpM + grp;
        #pragma unroll
        for (int ns = 0; ns < NSUB; ++ns) {
            int col = ns * 8 + 2 * qk;
            *reinterpret_cast<float2*>(C + (size_t)r0 * ldc + col) =
                make_float2(acc[0][ns][0] - lse0, acc[0][ns][1] - lse0);
            *reinterpret_cast<float2*>(C + (size_t)(r0 + 8) * ldc + col) =
                make_float2(acc[0][ns][2] - lse1, acc[0][ns][3] - lse1);
        }
    } else {
        #pragma unroll
        for (int ms = 0; ms < MSUB; ++ms)
            #pragma unroll
            for (int ns = 0; ns < NSUB; ++ns) {
                int row = brow + warpM + ms * 16 + grp;
                int col = warpN + ns * 8 + 2 * qk;
                *reinterpret_cast<float2*>(C + (size_t)row * ldc + col) =
                    make_float2(acc[ms][ns][0], acc[ms][ns][1]);
                *reinterpret_cast<float2*>(C + (size_t)(row + 8) * ldc + col) =
                    make_float2(acc[ms][ns][2], acc[ms][ns][3]);
            }
    }
}

// ---------------------------------------------------------------------------
// Dense tf32 GEMM, 3-term compensation, double-buffered, one sync per chunk.
// C[m][n] = sum_k A[m][k] * B'[n][k]   (Bt row-major = B^T).
// ---------------------------------------------------------------------------
template<int BM, int BN, int KTOT, int WM, int WN, bool RELU>
__global__ __launch_bounds__(256)
void gemm_mma(const float* __restrict__ A, const float* __restrict__ Bt,
              float* __restrict__ C, int lda, int ldb, int ldc)
{
    constexpr int LDS_   = 36;
    constexpr int NWN    = BN / WN;
    constexpr int MSUB   = WM / 16;
    constexpr int NSUB   = WN / 8;
    constexpr int NCHUNK = KTOT / 32;
    constexpr int A_FLT  = BM * LDS_;
    constexpr int B_FLT  = BN * LDS_;
    constexpr int STAGE_FLT = 2 * A_FLT + 2 * B_FLT;
    constexpr int APT    = BM * 8 / 256;
    constexpr int BPT    = BN * 8 / 256;

    extern __shared__ float sm[];

    const int tid   = threadIdx.x;
    const int wid   = tid >> 5;
    const int lane  = tid & 31;
    const int brow  = blockIdx.x * BM;
    const int bcol  = blockIdx.y * BN;
    const int warpM = (wid / NWN) * WM;
    const int warpN = (wid % NWN) * WN;
    const int grp   = lane >> 2;
    const int qk    = lane & 3;

    float acc[MSUB][NSUB][4] = {};
    float4 pa[APT], pb[BPT];

    #pragma unroll
    for (int j = 0; j < APT; ++j) {
        int i = tid + j * 256;
        pa[j] = *reinterpret_cast<const float4*>(
            A + (size_t)(brow + (i >> 3)) * lda + ((i & 7) << 2));
    }
    #pragma unroll
    for (int j = 0; j < BPT; ++j) {
        int i = tid + j * 256;
        pb[j] = *reinterpret_cast<const float4*>(
            Bt + (size_t)(bcol + (i >> 3)) * ldb + ((i & 7) << 2));
    }

    for (int c = 0; c < NCHUNK; ++c) {
        float* Ah = sm + (c & 1) * STAGE_FLT;
        float* Al = Ah + A_FLT;
        float* Bh = Al + A_FLT;
        float* Bl = Bh + B_FLT;

        #pragma unroll
        for (int j = 0; j < APT; ++j) {
            int i = tid + j * 256;
            int r = i >> 3, f = (i & 7) << 2;
            float4 v = pa[j];
            float* ph = Ah + r * LDS_ + f;
            float* pl = Al + r * LDS_ + f;
            float hx = __uint_as_float(f2tf32(v.x));
            float hy = __uint_as_float(f2tf32(v.y));
            float hz = __uint_as_float(f2tf32(v.z));
            float hw = __uint_as_float(f2tf32(v.w));
            ph[0] = hx; ph[1] = hy; ph[2] = hz; ph[3] = hw;
            pl[0] = __uint_as_float(f2tf32(v.x - hx));
            pl[1] = __uint_as_float(f2tf32(v.y - hy));
            pl[2] = __uint_as_float(f2tf32(v.z - hz));
            pl[3] = __uint_as_float(f2tf32(v.w - hw));
        }
        #pragma unroll
        for (int j = 0; j < BPT; ++j) {
            int i = tid + j * 256;
            int r = i >> 3, f = (i & 7) << 2;
            float4 v = pb[j];
            float* ph = Bh + r * LDS_ + f;
            float* pl = Bl + r * LDS_ + f;
            float hx = __uint_as_float(f2tf32(v.x));
            float hy = __uint_as_float(f2tf32(v.y));
            float hz = __uint_as_float(f2tf32(v.z));
            float hw = __uint_as_float(f2tf32(v.w));
            ph[0] = hx; ph[1] = hy; ph[2] = hz; ph[3] = hw;
            pl[0] = __uint_as_float(f2tf32(v.x - hx));
            pl[1] = __uint_as_float(f2tf32(v.y - hy));
            pl[2] = __uint_as_float(f2tf32(v.z - hz));
            pl[3] = __uint_as_float(f2tf32(v.w - hw));
        }
        if (c + 1 < NCHUNK) {
            #pragma unroll
            for (int j = 0; j < APT; ++j) {
                int i = tid + j * 256;
                pa[j] = *reinterpret_cast<const float4*>(
                    A + (size_t)(brow + (i >> 3)) * lda + (c + 1) * 32 + ((i & 7) << 2));
            }
            #pragma unroll
            for (int j = 0; j < BPT; ++j) {
                int i = tid + j * 256;
                pb[j] = *reinterpret_cast<const float4*>(
                    Bt + (size_t)(bcol + (i >> 3)) * ldb + (c + 1) * 32 + ((i & 7) << 2));
            }
        }
        __syncthreads();

        #pragma unroll
        for (int ks = 0; ks < 4; ++ks) {
            const int kb = ks * 8;
            uint32_t afh[MSUB][4], afl[MSUB][4];
            #pragma unroll
            for (int ms = 0; ms < MSUB; ++ms) {
                int r0 = (warpM + ms * 16 + grp) * LDS_ + kb + qk;
                int r1 = r0 + 8 * LDS_;
                afh[ms][0] = __float_as_uint(Ah[r0]);
                afh[ms][1] = __float_as_uint(Ah[r1]);
                afh[ms][2] = __float_as_uint(Ah[r0 + 4]);
                afh[ms][3] = __float_as_uint(Ah[r1 + 4]);
                afl[ms][0] = __float_as_uint(Al[r0]);
                afl[ms][1] = __float_as_uint(Al[r1]);
                afl[ms][2] = __float_as_uint(Al[r0 + 4]);
                afl[ms][3] = __float_as_uint(Al[r1 + 4]);
            }
            uint32_t bfh[NSUB][2], bfl[NSUB][2];
            #pragma unroll
            for (int ns = 0; ns < NSUB; ++ns) {
                int b0 = (warpN + ns * 8 + grp) * LDS_ + kb + qk;
                bfh[ns][0] = __float_as_uint(Bh[b0]);
                bfh[ns][1] = __float_as_uint(Bh[b0 + 4]);
                bfl[ns][0] = __float_as_uint(Bl[b0]);
                bfl[ns][1] = __float_as_uint(Bl[b0 + 4]);
            }
            #pragma unroll
            for (int ms = 0; ms < MSUB; ++ms)
                #pragma unroll
                for (int ns = 0; ns < NSUB; ++ns) {
                    mma_tf32(acc[ms][ns], afh[ms], bfh[ns]);
                    mma_tf32(acc[ms][ns], afh[ms], bfl[ns]);
                    mma_tf32(acc[ms][ns], afl[ms], bfh[ns]);
                }
        }
    }

    #pragma unroll
    for (int ms = 0; ms < MSUB; ++ms)
        #pragma unroll
        for (int ns = 0; ns < NSUB; ++ns) {
            int row = brow + warpM + ms * 16 + grp;
            int col = bcol + warpN + ns * 8 + 2 * qk;
            float2 v0 = make_float2(acc[ms][ns][0], acc[ms][ns][1]);
            float2 v1 = make_float2(acc[ms][ns][2], acc[ms][ns][3]);
            if (RELU) {
                v0.x = fmaxf(v0.x, 0.f); v0.y = fmaxf(v0.y, 0.f);
                v1.x = fmaxf(v1.x, 0.f); v1.y = fmaxf(v1.y, 0.f);
            }
            *reinterpret_cast<float2*>(C + (size_t)row * ldc + col)       = v0;
            *reinterpret_cast<float2*>(C + (size_t)(row + 8) * ldc + col) = v1;
        }
}

// ---------------------------------------------------------------------------
extern "C" void kernel_launch(void* const* d_in, const int* in_sizes, int n_in,
                              void* d_out, int out_size)
{
    const float* x    = (const float*)d_in[0];
    const int*   edge = (const int*)  d_in[1];
    const float* W1   = (const float*)d_in[2];
    const float* W2   = (const float*)d_in[3];
    float* out = (float*)d_out;

    float *gxT, *gW1t, *gW2t, *gX, *gH, *gTt;
    cudaGetSymbolAddress((void**)&gxT,  g_xT);
    cudaGetSymbolAddress((void**)&gW1t, g_W1t);
    cudaGetSymbolAddress((void**)&gW2t, g_W2t);
    cudaGetSymbolAddress((void**)&gX,   g_X);
    cudaGetSymbolAddress((void**)&gH,   g_H);
    cudaGetSymbolAddress((void**)&gTt,  g_Tt);

    constexpr int SM_AGG1 = 2 * (2 * 128 * 36) * 4;            // 73728
    constexpr int SM_AGG2 = 2 * (2 * 64 * 36) * 4;             // 36864
    constexpr int SM_G1   = 2 * (2 * 128 * 36 + 2 * 128 * 36) * 4;  // 147456
    constexpr int SM_G2   = 2 * (2 * 64 * 36 + 2 * 64 * 36) * 4;    // 73728
    cudaFuncSetAttribute(agg_mma<64, 128, 64, false>,
                         cudaFuncAttributeMaxDynamicSharedMemorySize, SM_AGG1);
    cudaFuncSetAttribute(agg_mma<128, 64, 64, true>,
                         cudaFuncAttributeMaxDynamicSharedMemorySize, SM_AGG2);
    cudaFuncSetAttribute(gemm_mma<128, 128, 128, 64, 32, true>,
                         cudaFuncAttributeMaxDynamicSharedMemorySize, SM_G1);
    cudaFuncSetAttribute(gemm_mma<64, 64, 256, 16, 32, false>,
                         cudaFuncAttributeMaxDynamicSharedMemorySize, SM_G2);

    // K0: transposes (x, W1, W2)
    transpose_kernel<<<1072, 256>>>(x, W1, W2, gxT, gW1t, gW2t);
    // K1: gX = adj @ x      (bitmap-A, B = xT)         grid 128
    agg_mma<64, 128, 64, false><<<128, 256, SM_AGG1>>>(gxT, edge, gX, NFEAT);
    // K2: gH = relu(gX @ W1)                            grid (64,2)
    gemm_mma<128, 128, 128, 64, 32, true>
        <<<dim3(64, 2), 256, SM_G1>>>(gX, gW1t, gH, NFEAT, NFEAT, NHID);
    // K3: Tt = (gH @ W2)^T  (A = W2t, B = gH as-is)     grid (1,128)
    gemm_mma<64, 64, 256, 16, 32, false>
        <<<dim3(1, 128), 256, SM_G2>>>(gW2t, gH, gTt, NHID, NHID, NN);
    // K4: out = log_softmax(adj @ T)  (bitmap-A, B = Tt, fused lsm)  grid 64
    agg_mma<128, 64, 64, true><<<64, 256, SM_AGG2>>>(gTt, edge, out, NCLASS);
}

// round 10
// speedup vs baseline: 1.5579x; 1.5579x over previous
#include <cuda_runtime.h>
#include <cuda_bf16.h>
#include <cstdint>

#define NN      8192
#define NODE    256
#define DEG     16
#define NFEAT   128
#define NHID    256
#define NCLASS  64

// ---------------- device scratch (no allocation allowed) --------------------
__device__ float g_X  [NN * NFEAT];       // adj @ x
__device__ float g_H  [NN * NHID];        // relu(gX @ W1)
__device__ float g_T  [NN * NCLASS];      // gH @ W2
__device__ float g_W1t[NHID * NFEAT];     // W1^T
__device__ float g_W2t[NCLASS * NHID];    // W2^T

__device__ __forceinline__ uint32_t f2tf32(float a) {
    uint32_t u; asm("cvt.rna.tf32.f32 %0, %1;" : "=r"(u) : "f"(a)); return u;
}
__device__ __forceinline__ void mma_tf32(float c[4], const uint32_t a[4], const uint32_t b[2]) {
    asm volatile(
        "mma.sync.aligned.m16n8k8.row.col.f32.tf32.tf32.f32 "
        "{%0,%1,%2,%3}, {%4,%5,%6,%7}, {%8,%9}, {%0,%1,%2,%3};"
        : "+f"(c[0]), "+f"(c[1]), "+f"(c[2]), "+f"(c[3])
        : "r"(a[0]), "r"(a[1]), "r"(a[2]), "r"(a[3]), "r"(b[0]), "r"(b[1]));
}

// Dynamic smem sizes for agg1 (all gather state lives in dynamic smem)
#define A1_SMX_FLT   (NODE * 32)              // 32768 B
#define A1_EDGE_INT  (NODE * DEG)             // 16384 B
#define A1_MASK_U    (NODE)                   // 1024 B
#define A1_SMEM_B    ((A1_SMX_FLT + A1_EDGE_INT + A1_MASK_U + NODE) * 4)  // pad

// ---------------------------------------------------------------------------
// K1: blocks 0..127 : agg1 — smem-staged adj @ x. CTA = (block, 32-col slice).
//     blocks 128..159: W1^T tiles.  blocks 160..175: W2^T tiles.
// ---------------------------------------------------------------------------
__global__ __launch_bounds__(256)
void agg1_kernel(const float* __restrict__ x, const int* __restrict__ edge,
                 const float* __restrict__ W1, const float* __restrict__ W2,
                 float* __restrict__ gX, float* __restrict__ W1t,
                 float* __restrict__ W2t)
{
    extern __shared__ float dyn[];
    const int bid = blockIdx.x;
    const int tid = threadIdx.x;

    if (bid < 128) {
        float*    smx   = dyn;                                  // [256][32]
        int*      sedge = reinterpret_cast<int*>(dyn + A1_SMX_FLT);      // [256][16]
        unsigned* smask = reinterpret_cast<unsigned*>(sedge + A1_EDGE_INT); // [256]

        const int blk  = bid >> 2;
        const int g    = bid & 3;               // 32-col group
        const int base = blk * NODE;

        // stage x slice: 256 rows x 32 cols
#pragma unroll
        for (int i = tid; i < NODE * 8; i += 256) {
            int r = i >> 3, qd = i & 7;
            *reinterpret_cast<float4*>(&smx[r * 32 + qd * 4]) =
                *reinterpret_cast<const float4*>(
                    x + (size_t)(base + r) * NFEAT + g * 32 + qd * 4);
        }
        // edges + dedup mask (thread = node)
        {
            const int4* ep = reinterpret_cast<const int4*>(edge + (size_t)(base + tid) * DEG);
            int4 v0 = ep[0], v1 = ep[1], v2 = ep[2], v3 = ep[3];
            int e[16] = {v0.x, v0.y, v0.z, v0.w, v1.x, v1.y, v1.z, v1.w,
                         v2.x, v2.y, v2.z, v2.w, v3.x, v3.y, v3.z, v3.w};
            unsigned mask = 0;
#pragma unroll
            for (int i = 0; i < 16; ++i) {
                bool keep = e[i] >= 0;
#pragma unroll
                for (int p = 0; p < i; ++p) keep = keep && (e[i] != e[p]);
                if (keep) mask |= 1u << i;
                sedge[tid * DEG + i] = e[i];
            }
            smask[tid] = mask;
        }
        __syncthreads();

        // gather from smem: thread = (node, col-quad); 8 passes of 32 nodes
#pragma unroll
        for (int p = 0; p < 8; ++p) {
            const int nl = p * 32 + (tid >> 3);
            const int qd = tid & 7;
            const unsigned mask = smask[nl];
            float4 a = make_float4(0.f, 0.f, 0.f, 0.f);
#pragma unroll
            for (int t = 0; t < DEG; ++t) {
                if (mask & (1u << t)) {
                    int j = sedge[nl * DEG + t];
                    float4 v = *reinterpret_cast<const float4*>(&smx[j * 32 + qd * 4]);
                    a.x += v.x; a.y += v.y; a.z += v.z; a.w += v.w;
                }
            }
            *reinterpret_cast<float4*>(
                gX + (size_t)(base + nl) * NFEAT + g * 32 + qd * 4) = a;
        }
    } else {
        // W transposes: 32x32 tiles (reuse dynamic smem)
        float* t = dyn;                         // [32][33]
        const float* src; float* dst; int R, C, tr, tc;
        if (bid < 160) { int b = bid - 128; src = W1; dst = W1t; R = NFEAT; C = NHID;  tr = b >> 3; tc = b & 7; }
        else           { int b = bid - 160; src = W2; dst = W2t; R = NHID;  C = NCLASS; tr = b >> 1; tc = b & 1; }
        const int r  = tid >> 3;
        const int fq = tid & 7;
        float4 v = *reinterpret_cast<const float4*>(src + (size_t)(tr * 32 + r) * C + tc * 32 + fq * 4);
        t[r * 33 + fq * 4 + 0] = v.x; t[r * 33 + fq * 4 + 1] = v.y;
        t[r * 33 + fq * 4 + 2] = v.z; t[r * 33 + fq * 4 + 3] = v.w;
        __syncthreads();
        float4 o;
        o.x = t[(fq * 4 + 0) * 33 + r]; o.y = t[(fq * 4 + 1) * 33 + r];
        o.z = t[(fq * 4 + 2) * 33 + r]; o.w = t[(fq * 4 + 3) * 33 + r];
        *reinterpret_cast<float4*>(dst + (size_t)(tc * 32 + r) * R + tr * 32 + fq * 4) = o;
    }
}

// ---------------------------------------------------------------------------
// Warp-level tf32 mma.sync GEMM, 3xTF32 compensation (proven R7 config).
// ---------------------------------------------------------------------------
template<int BM, int BN, int KTOT, int WM, int WN, bool RELU>
__global__ __launch_bounds__(256)
void gemm_mma(const float* __restrict__ A, const float* __restrict__ Bt,
              float* __restrict__ C, int ldc)
{
    constexpr int LDS_   = 36;
    constexpr int NWN    = BN / WN;
    constexpr int MSUB   = WM / 16;
    constexpr int NSUB   = WN / 8;
    constexpr int NCHUNK = KTOT / 32;
    constexpr int A_FLT  = BM * LDS_;
    constexpr int B_FLT  = BN * LDS_;
    constexpr int STAGE_FLT = 2 * A_FLT + 2 * B_FLT;
    constexpr int APT    = BM * 8 / 256;
    constexpr int BPT    = BN * 8 / 256;

    extern __shared__ float sm[];

    const int tid   = threadIdx.x;
    const int wid   = tid >> 5;
    const int lane  = tid & 31;
    const int brow  = blockIdx.x * BM;
    const int bcol  = blockIdx.y * BN;
    const int warpM = (wid / NWN) * WM;
    const int warpN = (wid % NWN) * WN;
    const int grp   = lane >> 2;
    const int qk    = lane & 3;

    float acc[MSUB][NSUB][4] = {};
    float4 pa[APT], pb[BPT];

#pragma unroll
    for (int j = 0; j < APT; ++j) {
        int i = tid + j * 256;
        pa[j] = *reinterpret_cast<const float4*>(
            A + (size_t)(brow + (i >> 3)) * KTOT + ((i & 7) << 2));
    }
#pragma unroll
    for (int j = 0; j < BPT; ++j) {
        int i = tid + j * 256;
        pb[j] = *reinterpret_cast<const float4*>(
            Bt + (size_t)(bcol + (i >> 3)) * KTOT + ((i & 7) << 2));
    }

    for (int c = 0; c < NCHUNK; ++c) {
        float* Ah = sm + (c & 1) * STAGE_FLT;
        float* Al = Ah + A_FLT;
        float* Bh = Al + A_FLT;
        float* Bl = Bh + B_FLT;

#pragma unroll
        for (int j = 0; j < APT; ++j) {
            int i = tid + j * 256;
            int r = i >> 3, f = (i & 7) << 2;
            float4 v = pa[j];
            float* ph = Ah + r * LDS_ + f;
            float* pl = Al + r * LDS_ + f;
            float hx = __uint_as_float(f2tf32(v.x));
            float hy = __uint_as_float(f2tf32(v.y));
            float hz = __uint_as_float(f2tf32(v.z));
            float hw = __uint_as_float(f2tf32(v.w));
            ph[0] = hx; ph[1] = hy; ph[2] = hz; ph[3] = hw;
            pl[0] = __uint_as_float(f2tf32(v.x - hx));
            pl[1] = __uint_as_float(f2tf32(v.y - hy));
            pl[2] = __uint_as_float(f2tf32(v.z - hz));
            pl[3] = __uint_as_float(f2tf32(v.w - hw));
        }
#pragma unroll
        for (int j = 0; j < BPT; ++j) {
            int i = tid + j * 256;
            int r = i >> 3, f = (i & 7) << 2;
            float4 v = pb[j];
            float* ph = Bh + r * LDS_ + f;
            float* pl = Bl + r * LDS_ + f;
            float hx = __uint_as_float(f2tf32(v.x));
            float hy = __uint_as_float(f2tf32(v.y));
            float hz = __uint_as_float(f2tf32(v.z));
            float hw = __uint_as_float(f2tf32(v.w));
            ph[0] = hx; ph[1] = hy; ph[2] = hz; ph[3] = hw;
            pl[0] = __uint_as_float(f2tf32(v.x - hx));
            pl[1] = __uint_as_float(f2tf32(v.y - hy));
            pl[2] = __uint_as_float(f2tf32(v.z - hz));
            pl[3] = __uint_as_float(f2tf32(v.w - hw));
        }
        if (c + 1 < NCHUNK) {
#pragma unroll
            for (int j = 0; j < APT; ++j) {
                int i = tid + j * 256;
                pa[j] = *reinterpret_cast<const float4*>(
                    A + (size_t)(brow + (i >> 3)) * KTOT + (c + 1) * 32 + ((i & 7) << 2));
            }
#pragma unroll
            for (int j = 0; j < BPT; ++j) {
                int i = tid + j * 256;
                pb[j] = *reinterpret_cast<const float4*>(
                    Bt + (size_t)(bcol + (i >> 3)) * KTOT + (c + 1) * 32 + ((i & 7) << 2));
            }
        }
        __syncthreads();

#pragma unroll
        for (int ks = 0; ks < 4; ++ks) {
            const int kb = ks * 8;
            uint32_t afh[MSUB][4], afl[MSUB][4];
#pragma unroll
            for (int ms = 0; ms < MSUB; ++ms) {
                int r0 = (warpM + ms * 16 + grp) * LDS_ + kb + qk;
                int r1 = r0 + 8 * LDS_;
                afh[ms][0] = __float_as_uint(Ah[r0]);
                afh[ms][1] = __float_as_uint(Ah[r1]);
                afh[ms][2] = __float_as_uint(Ah[r0 + 4]);
                afh[ms][3] = __float_as_uint(Ah[r1 + 4]);
                afl[ms][0] = __float_as_uint(Al[r0]);
                afl[ms][1] = __float_as_uint(Al[r1]);
                afl[ms][2] = __float_as_uint(Al[r0 + 4]);
                afl[ms][3] = __float_as_uint(Al[r1 + 4]);
            }
            uint32_t bfh[NSUB][2], bfl[NSUB][2];
#pragma unroll
            for (int ns = 0; ns < NSUB; ++ns) {
                int b0 = (warpN + ns * 8 + grp) * LDS_ + kb + qk;
                bfh[ns][0] = __float_as_uint(Bh[b0]);
                bfh[ns][1] = __float_as_uint(Bh[b0 + 4]);
                bfl[ns][0] = __float_as_uint(Bl[b0]);
                bfl[ns][1] = __float_as_uint(Bl[b0 + 4]);
            }
#pragma unroll
            for (int ms = 0; ms < MSUB; ++ms)
#pragma unroll
                for (int ns = 0; ns < NSUB; ++ns) {
                    mma_tf32(acc[ms][ns], afh[ms], bfh[ns]);
                    mma_tf32(acc[ms][ns], afh[ms], bfl[ns]);
                    mma_tf32(acc[ms][ns], afl[ms], bfh[ns]);
                }
        }
    }

#pragma unroll
    for (int ms = 0; ms < MSUB; ++ms)
#pragma unroll
        for (int ns = 0; ns < NSUB; ++ns) {
            int row = brow + warpM + ms * 16 + grp;
            int col = bcol + warpN + ns * 8 + 2 * qk;
            float2 v0 = make_float2(acc[ms][ns][0], acc[ms][ns][1]);
            float2 v1 = make_float2(acc[ms][ns][2], acc[ms][ns][3]);
            if (RELU) {
                v0.x = fmaxf(v0.x, 0.f); v0.y = fmaxf(v0.y, 0.f);
                v1.x = fmaxf(v1.x, 0.f); v1.y = fmaxf(v1.y, 0.f);
            }
            *reinterpret_cast<float2*>(C + (size_t)row * ldc + col)       = v0;
            *reinterpret_cast<float2*>(C + (size_t)(row + 8) * ldc + col) = v1;
        }
}

// ---------------------------------------------------------------------------
// K4: agg2 + log_softmax — smem-staged adj @ T. CTA = (block, 64-node quarter).
// Dynamic smem: T block (64 KB) + edges (4 KB) + masks (256 B).
// ---------------------------------------------------------------------------
#define A2_SMT_FLT   (NODE * NCLASS)          // 65536 B
#define A2_EDGE_INT  (64 * DEG)               // 4096 B
#define A2_SMEM_B    ((A2_SMT_FLT + A2_EDGE_INT + 64 + 64) * 4)

__global__ __launch_bounds__(256)
void agg2_kernel(const float* __restrict__ T, const int* __restrict__ edge,
                 float* __restrict__ out)
{
    extern __shared__ float dyn[];
    float*    smt   = dyn;                                        // [256][64]
    int*      sedge = reinterpret_cast<int*>(dyn + A2_SMT_FLT);   // [64][16]
    unsigned* smask = reinterpret_cast<unsigned*>(sedge + A2_EDGE_INT); // [64]

    const int bid   = blockIdx.x;           // 0..127
    const int tid   = threadIdx.x;
    const int blk   = bid >> 2;
    const int q     = bid & 3;
    const int base  = blk * NODE;
    const int nbase = base + q * 64;

    // stage full T block: 256 rows x 64 cols
#pragma unroll
    for (int i = tid; i < NODE * 16; i += 256) {
        int r = i >> 4, qd = i & 15;
        *reinterpret_cast<float4*>(&smt[r * 64 + qd * 4]) =
            *reinterpret_cast<const float4*>(T + (size_t)(base + r) * NCLASS + qd * 4);
    }
    if (tid < 64) {
        const int4* ep = reinterpret_cast<const int4*>(edge + (size_t)(nbase + tid) * DEG);
        int4 v0 = ep[0], v1 = ep[1], v2 = ep[2], v3 = ep[3];
        int e[16] = {v0.x, v0.y, v0.z, v0.w, v1.x, v1.y, v1.z, v1.w,
                     v2.x, v2.y, v2.z, v2.w, v3.x, v3.y, v3.z, v3.w};
        unsigned mask = 0;
#pragma unroll
        for (int i = 0; i < 16; ++i) {
            bool keep = e[i] >= 0;
#pragma unroll
            for (int p = 0; p < i; ++p) keep = keep && (e[i] != e[p]);
            if (keep) mask |= 1u << i;
            sedge[tid * DEG + i] = e[i];
        }
        smask[tid] = mask;
    }
    __syncthreads();

    // thread = (node, col-quad); 4 passes of 16 nodes
#pragma unroll
    for (int p = 0; p < 4; ++p) {
        const int nl = p * 16 + (tid >> 4);
        const int qd = tid & 15;
        const unsigned mask = smask[nl];
        float4 a = make_float4(0.f, 0.f, 0.f, 0.f);
#pragma unroll
        for (int t = 0; t < DEG; ++t) {
            if (mask & (1u << t)) {
                int j = sedge[nl * DEG + t];
                float4 v = *reinterpret_cast<const float4*>(&smt[j * 64 + qd * 4]);
                a.x += v.x; a.y += v.y; a.z += v.z; a.w += v.w;
            }
        }
        // log_softmax across the 16 threads (64 cols) of this node
        float mx = fmaxf(fmaxf(a.x, a.y), fmaxf(a.z, a.w));
#pragma unroll
        for (int o = 8; o; o >>= 1)
            mx = fmaxf(mx, __shfl_xor_sync(0xffffffffu, mx, o));
        float s = expf(a.x - mx) + expf(a.y - mx) + expf(a.z - mx) + expf(a.w - mx);
#pragma unroll
        for (int o = 8; o; o >>= 1)
            s += __shfl_xor_sync(0xffffffffu, s, o);
        float lse = logf(s) + mx;
        *reinterpret_cast<float4*>(out + (size_t)(nbase + nl) * NCLASS + qd * 4) =
            make_float4(a.x - lse, a.y - lse, a.z - lse, a.w - lse);
    }
}

// ---------------------------------------------------------------------------
extern "C" void kernel_launch(void* const* d_in, const int* in_sizes, int n_in,
                              void* d_out, int out_size)
{
    const float* x    = (const float*)d_in[0];
    const int*   edge = (const int*)  d_in[1];
    const float* W1   = (const float*)d_in[2];
    const float* W2   = (const float*)d_in[3];
    float* out = (float*)d_out;

    float *gX, *gH, *gT, *gW1t, *gW2t;
    cudaGetSymbolAddress((void**)&gX,   g_X);
    cudaGetSymbolAddress((void**)&gH,   g_H);
    cudaGetSymbolAddress((void**)&gT,   g_T);
    cudaGetSymbolAddress((void**)&gW1t, g_W1t);
    cudaGetSymbolAddress((void**)&gW2t, g_W2t);

    constexpr int SMEM1 = 2 * (2 * 128 * 36 + 2 * 128 * 36) * 4;  // 147456
    constexpr int SMEM2 = 2 * (2 * 64 * 36 + 2 * 64 * 36) * 4;    // 73728
    cudaFuncSetAttribute(agg1_kernel,
                         cudaFuncAttributeMaxDynamicSharedMemorySize, A1_SMEM_B);
    cudaFuncSetAttribute(gemm_mma<128, 128, 128, 64, 32, true>,
                         cudaFuncAttributeMaxDynamicSharedMemorySize, SMEM1);
    cudaFuncSetAttribute(gemm_mma<64, 64, 256, 32, 16, false>,
                         cudaFuncAttributeMaxDynamicSharedMemorySize, SMEM2);
    cudaFuncSetAttribute(agg2_kernel,
                         cudaFuncAttributeMaxDynamicSharedMemorySize, A2_SMEM_B);

    // K1: gX = adj @ x (smem-staged) + W transposes
    agg1_kernel<<<176, 256, A1_SMEM_B>>>(x, edge, W1, W2, gX, gW1t, gW2t);
    // K2: gH = relu(gX @ W1)
    gemm_mma<128, 128, 128, 64, 32, true>
        <<<dim3(64, 2), 256, SMEM1>>>(gX, gW1t, gH, NHID);
    // K3: gT = gH @ W2
    gemm_mma<64, 64, 256, 32, 16, false>
        <<<dim3(128, 1), 256, SMEM2>>>(gH, gW2t, gT, NCLASS);
    // K4: out = log_softmax(adj @ gT)  (smem-staged, fused lsm)
    agg2_kernel<<<128, 256, A2_SMEM_B>>>(gT, edge, out);
}

// round 11
// speedup vs baseline: 1.9750x; 1.2677x over previous
#include <cuda_runtime.h>
#include <cuda_bf16.h>
#include <cstdint>

#define NN      8192
#define NODE    256
#define DEG     16
#define NFEAT   128
#define NHID    256
#define NCLASS  64

// ---------------- device scratch (no allocation allowed) --------------------
__device__ float    g_X  [NN * NFEAT];    // adj @ x
__device__ float    g_H  [NN * NHID];     // relu(gX @ W1)
__device__ float    g_T  [NN * NCLASS];   // gH @ W2
__device__ unsigned g_keep[NN];           // dedup bitmask per node
__device__ float    g_W1t[NHID * NFEAT];  // W1^T
__device__ float    g_W2t[NCLASS * NHID]; // W2^T

// pack two f32 -> bf16x2 (hi arg = upper half)
__device__ __forceinline__ uint32_t bf2(float hi, float lo) {
    uint32_t r; asm("cvt.rn.bf16x2.f32 %0, %1, %2;" : "=r"(r) : "f"(hi), "f"(lo));
    return r;
}
__device__ __forceinline__ void mma_bf16(float c[4], const uint32_t a[4], const uint32_t b[2]) {
    asm volatile(
        "mma.sync.aligned.m16n8k16.row.col.f32.bf16.bf16.f32 "
        "{%0,%1,%2,%3}, {%4,%5,%6,%7}, {%8,%9}, {%0,%1,%2,%3};"
        : "+f"(c[0]), "+f"(c[1]), "+f"(c[2]), "+f"(c[3])
        : "r"(a[0]), "r"(a[1]), "r"(a[2]), "r"(a[3]), "r"(b[0]), "r"(b[1]));
}

// Dynamic smem sizes for agg1
#define A1_SMX_FLT   (NODE * 32)
#define A1_EDGE_INT  (NODE * DEG)
#define A1_SMEM_B    ((A1_SMX_FLT + A1_EDGE_INT + NODE + NODE) * 4)

// ---------------------------------------------------------------------------
// K1: blocks 0..127 : agg1 — smem-staged adj @ x. CTA = (block, 32-col slice).
//     Also writes dedup masks (g==0 CTAs). blocks 128..175: W transposes.
// ---------------------------------------------------------------------------
__global__ __launch_bounds__(256)
void agg1_kernel(const float* __restrict__ x, const int* __restrict__ edge,
                 const float* __restrict__ W1, const float* __restrict__ W2,
                 float* __restrict__ gX, unsigned* __restrict__ keep_out,
                 float* __restrict__ W1t, float* __restrict__ W2t)
{
    extern __shared__ float dyn[];
    const int bid = blockIdx.x;
    const int tid = threadIdx.x;

    if (bid < 128) {
        float*    smx   = dyn;                                           // [256][32]
        int*      sedge = reinterpret_cast<int*>(dyn + A1_SMX_FLT);      // [256][16]
        unsigned* smask = reinterpret_cast<unsigned*>(sedge + A1_EDGE_INT);

        const int blk  = bid >> 2;
        const int g    = bid & 3;
        const int base = blk * NODE;

#pragma unroll
        for (int i = tid; i < NODE * 8; i += 256) {
            int r = i >> 3, qd = i & 7;
            *reinterpret_cast<float4*>(&smx[r * 32 + qd * 4]) =
                *reinterpret_cast<const float4*>(
                    x + (size_t)(base + r) * NFEAT + g * 32 + qd * 4);
        }
        {
            const int4* ep = reinterpret_cast<const int4*>(edge + (size_t)(base + tid) * DEG);
            int4 v0 = ep[0], v1 = ep[1], v2 = ep[2], v3 = ep[3];
            int e[16] = {v0.x, v0.y, v0.z, v0.w, v1.x, v1.y, v1.z, v1.w,
                         v2.x, v2.y, v2.z, v2.w, v3.x, v3.y, v3.z, v3.w};
            unsigned mask = 0;
#pragma unroll
            for (int i = 0; i < 16; ++i) {
                bool keep = e[i] >= 0;
#pragma unroll
                for (int p = 0; p < i; ++p) keep = keep && (e[i] != e[p]);
                if (keep) mask |= 1u << i;
                sedge[tid * DEG + i] = e[i];
            }
            smask[tid] = mask;
            if (g == 0) keep_out[base + tid] = mask;
        }
        __syncthreads();

#pragma unroll
        for (int p = 0; p < 8; ++p) {
            const int nl = p * 32 + (tid >> 3);
            const int qd = tid & 7;
            const unsigned mask = smask[nl];
            float4 a = make_float4(0.f, 0.f, 0.f, 0.f);
#pragma unroll
            for (int t = 0; t < DEG; ++t) {
                if (mask & (1u << t)) {
                    int j = sedge[nl * DEG + t];
                    float4 v = *reinterpret_cast<const float4*>(&smx[j * 32 + qd * 4]);
                    a.x += v.x; a.y += v.y; a.z += v.z; a.w += v.w;
                }
            }
            *reinterpret_cast<float4*>(
                gX + (size_t)(base + nl) * NFEAT + g * 32 + qd * 4) = a;
        }
    } else {
        float* t = dyn;                         // [32][33]
        const float* src; float* dst; int R, C, tr, tc;
        if (bid < 160) { int b = bid - 128; src = W1; dst = W1t; R = NFEAT; C = NHID;  tr = b >> 3; tc = b & 7; }
        else           { int b = bid - 160; src = W2; dst = W2t; R = NHID;  C = NCLASS; tr = b >> 1; tc = b & 1; }
        const int r  = tid >> 3;
        const int fq = tid & 7;
        float4 v = *reinterpret_cast<const float4*>(src + (size_t)(tr * 32 + r) * C + tc * 32 + fq * 4);
        t[r * 33 + fq * 4 + 0] = v.x; t[r * 33 + fq * 4 + 1] = v.y;
        t[r * 33 + fq * 4 + 2] = v.z; t[r * 33 + fq * 4 + 3] = v.w;
        __syncthreads();
        float4 o;
        o.x = t[(fq * 4 + 0) * 33 + r]; o.y = t[(fq * 4 + 1) * 33 + r];
        o.z = t[(fq * 4 + 2) * 33 + r]; o.w = t[(fq * 4 + 3) * 33 + r];
        *reinterpret_cast<float4*>(dst + (size_t)(tc * 32 + r) * R + tr * 32 + fq * 4) = o;
    }
}

// ---------------------------------------------------------------------------
// bf16 mma.sync GEMM (m16n8k16), 3xBF16 compensation, double-buffered.
// smem layout: packed bf16x2 words, row stride 20 words (bank-conflict-free).
// ---------------------------------------------------------------------------
template<int BM, int BN, int KTOT, int WM, int WN, bool RELU>
__global__ __launch_bounds__(256)
void gemm_bf16(const float* __restrict__ A, const float* __restrict__ Bt,
               float* __restrict__ C, int ldc)
{
    constexpr int LW     = 20;                // words per 32-k row (16 + 4 pad)
    constexpr int NWN    = BN / WN;
    constexpr int MSUB   = WM / 16;
    constexpr int NSUB   = WN / 8;
    constexpr int NCHUNK = KTOT / 32;
    constexpr int A_W    = BM * LW;
    constexpr int B_W    = BN * LW;
    constexpr int STAGE_W = 2 * A_W + 2 * B_W;
    constexpr int APT    = BM * 8 / 256;
    constexpr int BPT    = BN * 8 / 256;

    extern __shared__ uint32_t smw[];

    const int tid   = threadIdx.x;
    const int wid   = tid >> 5;
    const int lane  = tid & 31;
    const int brow  = blockIdx.x * BM;
    const int bcol  = blockIdx.y * BN;
    const int warpM = (wid / NWN) * WM;
    const int warpN = (wid % NWN) * WN;
    const int grp   = lane >> 2;
    const int qk    = lane & 3;

    float acc[MSUB][NSUB][4] = {};
    float4 pa[APT], pb[BPT];

#pragma unroll
    for (int j = 0; j < APT; ++j) {
        int i = tid + j * 256;
        pa[j] = *reinterpret_cast<const float4*>(
            A + (size_t)(brow + (i >> 3)) * KTOT + ((i & 7) << 2));
    }
#pragma unroll
    for (int j = 0; j < BPT; ++j) {
        int i = tid + j * 256;
        pb[j] = *reinterpret_cast<const float4*>(
            Bt + (size_t)(bcol + (i >> 3)) * KTOT + ((i & 7) << 2));
    }

    for (int c = 0; c < NCHUNK; ++c) {
        uint32_t* Ah = smw + (c & 1) * STAGE_W;
        uint32_t* Al = Ah + A_W;
        uint32_t* Bh = Al + A_W;
        uint32_t* Bl = Bh + B_W;

#pragma unroll
        for (int j = 0; j < APT; ++j) {
            int i = tid + j * 256;
            int r = i >> 3, f = i & 7;
            float4 v = pa[j];
            uint32_t h0 = bf2(v.y, v.x), h1 = bf2(v.w, v.z);
            float hx = __uint_as_float(h0 << 16), hy = __uint_as_float(h0 & 0xffff0000u);
            float hz = __uint_as_float(h1 << 16), hw = __uint_as_float(h1 & 0xffff0000u);
            uint32_t l0 = bf2(v.y - hy, v.x - hx), l1 = bf2(v.w - hw, v.z - hz);
            *reinterpret_cast<uint2*>(&Ah[r * LW + f * 2]) = make_uint2(h0, h1);
            *reinterpret_cast<uint2*>(&Al[r * LW + f * 2]) = make_uint2(l0, l1);
        }
#pragma unroll
        for (int j = 0; j < BPT; ++j) {
            int i = tid + j * 256;
            int r = i >> 3, f = i & 7;
            float4 v = pb[j];
            uint32_t h0 = bf2(v.y, v.x), h1 = bf2(v.w, v.z);
            float hx = __uint_as_float(h0 << 16), hy = __uint_as_float(h0 & 0xffff0000u);
            float hz = __uint_as_float(h1 << 16), hw = __uint_as_float(h1 & 0xffff0000u);
            uint32_t l0 = bf2(v.y - hy, v.x - hx), l1 = bf2(v.w - hw, v.z - hz);
            *reinterpret_cast<uint2*>(&Bh[r * LW + f * 2]) = make_uint2(h0, h1);
            *reinterpret_cast<uint2*>(&Bl[r * LW + f * 2]) = make_uint2(l0, l1);
        }
        if (c + 1 < NCHUNK) {
#pragma unroll
            for (int j = 0; j < APT; ++j) {
                int i = tid + j * 256;
                pa[j] = *reinterpret_cast<const float4*>(
                    A + (size_t)(brow + (i >> 3)) * KTOT + (c + 1) * 32 + ((i & 7) << 2));
            }
#pragma unroll
            for (int j = 0; j < BPT; ++j) {
                int i = tid + j * 256;
                pb[j] = *reinterpret_cast<const float4*>(
                    Bt + (size_t)(bcol + (i >> 3)) * KTOT + (c + 1) * 32 + ((i & 7) << 2));
            }
        }
        __syncthreads();

#pragma unroll
        for (int ks = 0; ks < 2; ++ks) {          // two k16 steps per 32-k chunk
            const int kw = ks * 8;                // word offset
            uint32_t aH[MSUB][4], aL[MSUB][4];
#pragma unroll
            for (int ms = 0; ms < MSUB; ++ms) {
                int r0 = (warpM + ms * 16 + grp) * LW + kw + qk;
                int r1 = r0 + 8 * LW;
                aH[ms][0] = Ah[r0];     aH[ms][1] = Ah[r1];
                aH[ms][2] = Ah[r0 + 4]; aH[ms][3] = Ah[r1 + 4];
                aL[ms][0] = Al[r0];     aL[ms][1] = Al[r1];
                aL[ms][2] = Al[r0 + 4]; aL[ms][3] = Al[r1 + 4];
            }
            uint32_t bH[NSUB][2], bL[NSUB][2];
#pragma unroll
            for (int ns = 0; ns < NSUB; ++ns) {
                int b0 = (warpN + ns * 8 + grp) * LW + kw + qk;
                bH[ns][0] = Bh[b0]; bH[ns][1] = Bh[b0 + 4];
                bL[ns][0] = Bl[b0]; bL[ns][1] = Bl[b0 + 4];
            }
#pragma unroll
            for (int ms = 0; ms < MSUB; ++ms)
#pragma unroll
                for (int ns = 0; ns < NSUB; ++ns) {
                    mma_bf16(acc[ms][ns], aH[ms], bH[ns]);
                    mma_bf16(acc[ms][ns], aH[ms], bL[ns]);
                    mma_bf16(acc[ms][ns], aL[ms], bH[ns]);
                }
        }
        __syncthreads();
    }

#pragma unroll
    for (int ms = 0; ms < MSUB; ++ms)
#pragma unroll
        for (int ns = 0; ns < NSUB; ++ns) {
            int row = brow + warpM + ms * 16 + grp;
            int col = bcol + warpN + ns * 8 + 2 * qk;
            float2 v0 = make_float2(acc[ms][ns][0], acc[ms][ns][1]);
            float2 v1 = make_float2(acc[ms][ns][2], acc[ms][ns][3]);
            if (RELU) {
                v0.x = fmaxf(v0.x, 0.f); v0.y = fmaxf(v0.y, 0.f);
                v1.x = fmaxf(v1.x, 0.f); v1.y = fmaxf(v1.y, 0.f);
            }
            *reinterpret_cast<float2*>(C + (size_t)row * ldc + col)       = v0;
            *reinterpret_cast<float2*>(C + (size_t)(row + 8) * ldc + col) = v1;
        }
}

// ---------------------------------------------------------------------------
// K4: agg2 + log_softmax (R7-proven). One warp per node; lanes =
// (neighbor-of-pair, col-quad). Uses masks from agg1.
// ---------------------------------------------------------------------------
__global__ __launch_bounds__(256)
void agg_lsm_kernel(const float* __restrict__ T, const int* __restrict__ edge,
                    const unsigned* __restrict__ keep_in, float* __restrict__ out)
{
    const int node = (blockIdx.x * blockDim.x + threadIdx.x) >> 5;
    const int lane = threadIdx.x & 31;
    const int nbh  = lane >> 4;
    const int cq   = lane & 15;
    const int base = (node >> 8) << 8;

    int e = edge[node * DEG + cq];
    unsigned mask = keep_in[node];

    float4 a = make_float4(0.f, 0.f, 0.f, 0.f);
#pragma unroll
    for (int t = 0; t < 8; ++t) {
        int nb = 2 * t + nbh;
        int j = __shfl_sync(0xffffffffu, e, nb);
        if (mask & (1u << nb)) {
            float4 v = *reinterpret_cast<const float4*>(
                T + (size_t)(base + j) * NCLASS + (cq << 2));
            a.x += v.x; a.y += v.y; a.z += v.z; a.w += v.w;
        }
    }
    a.x += __shfl_xor_sync(0xffffffffu, a.x, 16);
    a.y += __shfl_xor_sync(0xffffffffu, a.y, 16);
    a.z += __shfl_xor_sync(0xffffffffu, a.z, 16);
    a.w += __shfl_xor_sync(0xffffffffu, a.w, 16);

    float mx = fmaxf(fmaxf(a.x, a.y), fmaxf(a.z, a.w));
#pragma unroll
    for (int o = 8; o; o >>= 1)
        mx = fmaxf(mx, __shfl_xor_sync(0xffffffffu, mx, o));
    float s = expf(a.x - mx) + expf(a.y - mx) + expf(a.z - mx) + expf(a.w - mx);
#pragma unroll
    for (int o = 8; o; o >>= 1)
        s += __shfl_xor_sync(0xffffffffu, s, o);
    float lse = logf(s) + mx;

    if (lane < 16)
        *reinterpret_cast<float4*>(out + (size_t)node * NCLASS + (cq << 2)) =
            make_float4(a.x - lse, a.y - lse, a.z - lse, a.w - lse);
}

// ---------------------------------------------------------------------------
extern "C" void kernel_launch(void* const* d_in, const int* in_sizes, int n_in,
                              void* d_out, int out_size)
{
    const float* x    = (const float*)d_in[0];
    const int*   edge = (const int*)  d_in[1];
    const float* W1   = (const float*)d_in[2];
    const float* W2   = (const float*)d_in[3];
    float* out = (float*)d_out;

    float *gX, *gH, *gT, *gW1t, *gW2t;
    unsigned *gK;
    cudaGetSymbolAddress((void**)&gX,   g_X);
    cudaGetSymbolAddress((void**)&gH,   g_H);
    cudaGetSymbolAddress((void**)&gT,   g_T);
    cudaGetSymbolAddress((void**)&gK,   g_keep);
    cudaGetSymbolAddress((void**)&gW1t, g_W1t);
    cudaGetSymbolAddress((void**)&gW2t, g_W2t);

    // GEMM1: 128x128 tile, warp 64x32 -> grid (64,2); smem 2*(2*128+2*128)*20*4 = 81920
    // GEMM2: 64x64 tile,  warp 32x16 -> grid (128,1); smem 2*(2*64+2*64)*20*4 = 40960
    constexpr int SMEM1 = 2 * (2 * 128 + 2 * 128) * 20 * 4;
    constexpr int SMEM2 = 2 * (2 * 64 + 2 * 64) * 20 * 4;
    cudaFuncSetAttribute(agg1_kernel,
                         cudaFuncAttributeMaxDynamicSharedMemorySize, A1_SMEM_B);
    cudaFuncSetAttribute(gemm_bf16<128, 128, 128, 64, 32, true>,
                         cudaFuncAttributeMaxDynamicSharedMemorySize, SMEM1);
    cudaFuncSetAttribute(gemm_bf16<64, 64, 256, 32, 16, false>,
                         cudaFuncAttributeMaxDynamicSharedMemorySize, SMEM2);

    // K1: gX = adj @ x (smem-staged) + keep masks + W transposes
    agg1_kernel<<<176, 256, A1_SMEM_B>>>(x, edge, W1, W2, gX, gK, gW1t, gW2t);
    // K2: gH = relu(gX @ W1)
    gemm_bf16<128, 128, 128, 64, 32, true>
        <<<dim3(64, 2), 256, SMEM1>>>(gX, gW1t, gH, NHID);
    // K3: gT = gH @ W2
    gemm_bf16<64, 64, 256, 32, 16, false>
        <<<dim3(128, 1), 256, SMEM2>>>(gH, gW2t, gT, NCLASS);
    // K4: out = log_softmax(adj @ gT)
    agg_lsm_kernel<<<NN / 8, 256>>>(gT, edge, gK, out);
}

// round 12
// speedup vs baseline: 1.9923x; 1.0088x over previous
#include <cuda_runtime.h>
#include <cuda_bf16.h>
#include <cstdint>

#define NN      8192
#define NODE    256
#define DEG     16
#define NFEAT   128
#define NHID    256
#define NCLASS  64

// ---------------- device scratch (no allocation allowed) --------------------
__device__ float    g_X  [NN * NFEAT];    // adj @ x
__device__ float    g_H  [NN * NHID];     // relu(gX @ W1)
__device__ float    g_T  [NN * NCLASS];   // gH @ W2
__device__ unsigned g_keep[NN];           // dedup bitmask per node
__device__ float    g_W1t[NHID * NFEAT];  // W1^T
__device__ float    g_W2t[NCLASS * NHID]; // W2^T

// pack two f32 -> bf16x2 (hi arg = upper half)
__device__ __forceinline__ uint32_t bf2(float hi, float lo) {
    uint32_t r; asm("cvt.rn.bf16x2.f32 %0, %1, %2;" : "=r"(r) : "f"(hi), "f"(lo));
    return r;
}
__device__ __forceinline__ void mma_bf16(float c[4], const uint32_t a[4], const uint32_t b[2]) {
    asm volatile(
        "mma.sync.aligned.m16n8k16.row.col.f32.bf16.bf16.f32 "
        "{%0,%1,%2,%3}, {%4,%5,%6,%7}, {%8,%9}, {%0,%1,%2,%3};"
        : "+f"(c[0]), "+f"(c[1]), "+f"(c[2]), "+f"(c[3])
        : "r"(a[0]), "r"(a[1]), "r"(a[2]), "r"(a[3]), "r"(b[0]), "r"(b[1]));
}

// Dynamic smem sizes for agg1
#define A1_SMX_FLT   (NODE * 32)
#define A1_EDGE_INT  (NODE * DEG)
#define A1_SMEM_B    ((A1_SMX_FLT + A1_EDGE_INT + NODE + NODE) * 4)

// ---------------------------------------------------------------------------
// K1: blocks 0..127 : agg1 — smem-staged adj @ x. CTA = (block, 32-col slice).
//     Also writes dedup masks (g==0 CTAs). blocks 128..175: W transposes.
// ---------------------------------------------------------------------------
__global__ __launch_bounds__(256)
void agg1_kernel(const float* __restrict__ x, const int* __restrict__ edge,
                 const float* __restrict__ W1, const float* __restrict__ W2,
                 float* __restrict__ gX, unsigned* __restrict__ keep_out,
                 float* __restrict__ W1t, float* __restrict__ W2t)
{
    extern __shared__ float dyn[];
    const int bid = blockIdx.x;
    const int tid = threadIdx.x;

    if (bid < 128) {
        float*    smx   = dyn;                                           // [256][32]
        int*      sedge = reinterpret_cast<int*>(dyn + A1_SMX_FLT);      // [256][16]
        unsigned* smask = reinterpret_cast<unsigned*>(sedge + A1_EDGE_INT);

        const int blk  = bid >> 2;
        const int g    = bid & 3;
        const int base = blk * NODE;

#pragma unroll
        for (int i = tid; i < NODE * 8; i += 256) {
            int r = i >> 3, qd = i & 7;
            *reinterpret_cast<float4*>(&smx[r * 32 + qd * 4]) =
                *reinterpret_cast<const float4*>(
                    x + (size_t)(base + r) * NFEAT + g * 32 + qd * 4);
        }
        {
            const int4* ep = reinterpret_cast<const int4*>(edge + (size_t)(base + tid) * DEG);
            int4 v0 = ep[0], v1 = ep[1], v2 = ep[2], v3 = ep[3];
            int e[16] = {v0.x, v0.y, v0.z, v0.w, v1.x, v1.y, v1.z, v1.w,
                         v2.x, v2.y, v2.z, v2.w, v3.x, v3.y, v3.z, v3.w};
            unsigned mask = 0;
#pragma unroll
            for (int i = 0; i < 16; ++i) {
                bool keep = e[i] >= 0;
#pragma unroll
                for (int p = 0; p < i; ++p) keep = keep && (e[i] != e[p]);
                if (keep) mask |= 1u << i;
                sedge[tid * DEG + i] = (e[i] >= 0) ? e[i] : 0;   // clamp for safe loads
            }
            smask[tid] = mask;
            if (g == 0) keep_out[base + tid] = mask;
        }
        __syncthreads();

        // branchless gather: all 16 LDS always issued; masked via fmaf
#pragma unroll
        for (int p = 0; p < 8; ++p) {
            const int nl = p * 32 + (tid >> 3);
            const int qd = tid & 7;
            const unsigned mask = smask[nl];
            float4 a = make_float4(0.f, 0.f, 0.f, 0.f);
#pragma unroll
            for (int t = 0; t < DEG; ++t) {
                int   j  = sedge[nl * DEG + t];
                float fm = (float)((mask >> t) & 1u);
                float4 v = *reinterpret_cast<const float4*>(&smx[j * 32 + qd * 4]);
                a.x = fmaf(v.x, fm, a.x);
                a.y = fmaf(v.y, fm, a.y);
                a.z = fmaf(v.z, fm, a.z);
                a.w = fmaf(v.w, fm, a.w);
            }
            *reinterpret_cast<float4*>(
                gX + (size_t)(base + nl) * NFEAT + g * 32 + qd * 4) = a;
        }
    } else {
        float* t = dyn;                         // [32][33]
        const float* src; float* dst; int R, C, tr, tc;
        if (bid < 160) { int b = bid - 128; src = W1; dst = W1t; R = NFEAT; C = NHID;  tr = b >> 3; tc = b & 7; }
        else           { int b = bid - 160; src = W2; dst = W2t; R = NHID;  C = NCLASS; tr = b >> 1; tc = b & 1; }
        const int r  = tid >> 3;
        const int fq = tid & 7;
        float4 v = *reinterpret_cast<const float4*>(src + (size_t)(tr * 32 + r) * C + tc * 32 + fq * 4);
        t[r * 33 + fq * 4 + 0] = v.x; t[r * 33 + fq * 4 + 1] = v.y;
        t[r * 33 + fq * 4 + 2] = v.z; t[r * 33 + fq * 4 + 3] = v.w;
        __syncthreads();
        float4 o;
        o.x = t[(fq * 4 + 0) * 33 + r]; o.y = t[(fq * 4 + 1) * 33 + r];
        o.z = t[(fq * 4 + 2) * 33 + r]; o.w = t[(fq * 4 + 3) * 33 + r];
        *reinterpret_cast<float4*>(dst + (size_t)(tc * 32 + r) * R + tr * 32 + fq * 4) = o;
    }
}

// ---------------------------------------------------------------------------
// bf16 mma.sync GEMM (m16n8k16), 3xBF16 compensation, double-buffered.
// ---------------------------------------------------------------------------
template<int BM, int BN, int KTOT, int WM, int WN, bool RELU>
__global__ __launch_bounds__(256)
void gemm_bf16(const float* __restrict__ A, const float* __restrict__ Bt,
               float* __restrict__ C, int ldc)
{
    constexpr int LW     = 20;                // words per 32-k row (16 + 4 pad)
    constexpr int NWN    = BN / WN;
    constexpr int MSUB   = WM / 16;
    constexpr int NSUB   = WN / 8;
    constexpr int NCHUNK = KTOT / 32;
    constexpr int A_W    = BM * LW;
    constexpr int B_W    = BN * LW;
    constexpr int STAGE_W = 2 * A_W + 2 * B_W;
    constexpr int APT    = BM * 8 / 256;
    constexpr int BPT    = BN * 8 / 256;

    extern __shared__ uint32_t smw[];

    const int tid   = threadIdx.x;
    const int wid   = tid >> 5;
    const int lane  = tid & 31;
    const int brow  = blockIdx.x * BM;
    const int bcol  = blockIdx.y * BN;
    const int warpM = (wid / NWN) * WM;
    const int warpN = (wid % NWN) * WN;
    const int grp   = lane >> 2;
    const int qk    = lane & 3;

    float acc[MSUB][NSUB][4] = {};
    float4 pa[APT], pb[BPT];

#pragma unroll
    for (int j = 0; j < APT; ++j) {
        int i = tid + j * 256;
        pa[j] = *reinterpret_cast<const float4*>(
            A + (size_t)(brow + (i >> 3)) * KTOT + ((i & 7) << 2));
    }
#pragma unroll
    for (int j = 0; j < BPT; ++j) {
        int i = tid + j * 256;
        pb[j] = *reinterpret_cast<const float4*>(
            Bt + (size_t)(bcol + (i >> 3)) * KTOT + ((i & 7) << 2));
    }

    for (int c = 0; c < NCHUNK; ++c) {
        uint32_t* Ah = smw + (c & 1) * STAGE_W;
        uint32_t* Al = Ah + A_W;
        uint32_t* Bh = Al + A_W;
        uint32_t* Bl = Bh + B_W;

#pragma unroll
        for (int j = 0; j < APT; ++j) {
            int i = tid + j * 256;
            int r = i >> 3, f = i & 7;
            float4 v = pa[j];
            uint32_t h0 = bf2(v.y, v.x), h1 = bf2(v.w, v.z);
            float hx = __uint_as_float(h0 << 16), hy = __uint_as_float(h0 & 0xffff0000u);
            float hz = __uint_as_float(h1 << 16), hw = __uint_as_float(h1 & 0xffff0000u);
            uint32_t l0 = bf2(v.y - hy, v.x - hx), l1 = bf2(v.w - hw, v.z - hz);
            *reinterpret_cast<uint2*>(&Ah[r * LW + f * 2]) = make_uint2(h0, h1);
            *reinterpret_cast<uint2*>(&Al[r * LW + f * 2]) = make_uint2(l0, l1);
        }
#pragma unroll
        for (int j = 0; j < BPT; ++j) {
            int i = tid + j * 256;
            int r = i >> 3, f = i & 7;
            float4 v = pb[j];
            uint32_t h0 = bf2(v.y, v.x), h1 = bf2(v.w, v.z);
            float hx = __uint_as_float(h0 << 16), hy = __uint_as_float(h0 & 0xffff0000u);
            float hz = __uint_as_float(h1 << 16), hw = __uint_as_float(h1 & 0xffff0000u);
            uint32_t l0 = bf2(v.y - hy, v.x - hx), l1 = bf2(v.w - hw, v.z - hz);
            *reinterpret_cast<uint2*>(&Bh[r * LW + f * 2]) = make_uint2(h0, h1);
            *reinterpret_cast<uint2*>(&Bl[r * LW + f * 2]) = make_uint2(l0, l1);
        }
        if (c + 1 < NCHUNK) {
#pragma unroll
            for (int j = 0; j < APT; ++j) {
                int i = tid + j * 256;
                pa[j] = *reinterpret_cast<const float4*>(
                    A + (size_t)(brow + (i >> 3)) * KTOT + (c + 1) * 32 + ((i & 7) << 2));
            }
#pragma unroll
            for (int j = 0; j < BPT; ++j) {
                int i = tid + j * 256;
                pb[j] = *reinterpret_cast<const float4*>(
                    Bt + (size_t)(bcol + (i >> 3)) * KTOT + (c + 1) * 32 + ((i & 7) << 2));
            }
        }
        __syncthreads();

#pragma unroll
        for (int ks = 0; ks < 2; ++ks) {
            const int kw = ks * 8;
            uint32_t aH[MSUB][4], aL[MSUB][4];
#pragma unroll
            for (int ms = 0; ms < MSUB; ++ms) {
                int r0 = (warpM + ms * 16 + grp) * LW + kw + qk;
                int r1 = r0 + 8 * LW;
                aH[ms][0] = Ah[r0];     aH[ms][1] = Ah[r1];
                aH[ms][2] = Ah[r0 + 4]; aH[ms][3] = Ah[r1 + 4];
                aL[ms][0] = Al[r0];     aL[ms][1] = Al[r1];
                aL[ms][2] = Al[r0 + 4]; aL[ms][3] = Al[r1 + 4];
            }
            uint32_t bH[NSUB][2], bL[NSUB][2];
#pragma unroll
            for (int ns = 0; ns < NSUB; ++ns) {
                int b0 = (warpN + ns * 8 + grp) * LW + kw + qk;
                bH[ns][0] = Bh[b0]; bH[ns][1] = Bh[b0 + 4];
                bL[ns][0] = Bl[b0]; bL[ns][1] = Bl[b0 + 4];
            }
#pragma unroll
            for (int ms = 0; ms < MSUB; ++ms)
#pragma unroll
                for (int ns = 0; ns < NSUB; ++ns) {
                    mma_bf16(acc[ms][ns], aH[ms], bH[ns]);
                    mma_bf16(acc[ms][ns], aH[ms], bL[ns]);
                    mma_bf16(acc[ms][ns], aL[ms], bH[ns]);
                }
        }
        __syncthreads();
    }

#pragma unroll
    for (int ms = 0; ms < MSUB; ++ms)
#pragma unroll
        for (int ns = 0; ns < NSUB; ++ns) {
            int row = brow + warpM + ms * 16 + grp;
            int col = bcol + warpN + ns * 8 + 2 * qk;
            float2 v0 = make_float2(acc[ms][ns][0], acc[ms][ns][1]);
            float2 v1 = make_float2(acc[ms][ns][2], acc[ms][ns][3]);
            if (RELU) {
                v0.x = fmaxf(v0.x, 0.f); v0.y = fmaxf(v0.y, 0.f);
                v1.x = fmaxf(v1.x, 0.f); v1.y = fmaxf(v1.y, 0.f);
            }
            *reinterpret_cast<float2*>(C + (size_t)row * ldc + col)       = v0;
            *reinterpret_cast<float2*>(C + (size_t)(row + 8) * ldc + col) = v1;
        }
}

// ---------------------------------------------------------------------------
// K4: agg2 + log_softmax. One warp per node; lanes = (neighbor-of-pair,
// col-quad). Branchless masked gather: all loads issued, fmaf by mask bit.
// ---------------------------------------------------------------------------
__global__ __launch_bounds__(256)
void agg_lsm_kernel(const float* __restrict__ T, const int* __restrict__ edge,
                    const unsigned* __restrict__ keep_in, float* __restrict__ out)
{
    const int node = (blockIdx.x * blockDim.x + threadIdx.x) >> 5;
    const int lane = threadIdx.x & 31;
    const int nbh  = lane >> 4;
    const int cq   = lane & 15;
    const int base = (node >> 8) << 8;

    int e = edge[node * DEG + cq];
    unsigned mask = keep_in[node];

    float4 a = make_float4(0.f, 0.f, 0.f, 0.f);
#pragma unroll
    for (int t = 0; t < 8; ++t) {
        int nb = 2 * t + nbh;
        int j  = __shfl_sync(0xffffffffu, e, nb);
        unsigned bit = (mask >> nb) & 1u;
        int jj = bit ? j : 0;                     // safe index when masked out
        float fm = (float)bit;
        float4 v = *reinterpret_cast<const float4*>(
            T + (size_t)(base + jj) * NCLASS + (cq << 2));
        a.x = fmaf(v.x, fm, a.x);
        a.y = fmaf(v.y, fm, a.y);
        a.z = fmaf(v.z, fm, a.z);
        a.w = fmaf(v.w, fm, a.w);
    }
    a.x += __shfl_xor_sync(0xffffffffu, a.x, 16);
    a.y += __shfl_xor_sync(0xffffffffu, a.y, 16);
    a.z += __shfl_xor_sync(0xffffffffu, a.z, 16);
    a.w += __shfl_xor_sync(0xffffffffu, a.w, 16);

    float mx = fmaxf(fmaxf(a.x, a.y), fmaxf(a.z, a.w));
#pragma unroll
    for (int o = 8; o; o >>= 1)
        mx = fmaxf(mx, __shfl_xor_sync(0xffffffffu, mx, o));
    float s = expf(a.x - mx) + expf(a.y - mx) + expf(a.z - mx) + expf(a.w - mx);
#pragma unroll
    for (int o = 8; o; o >>= 1)
        s += __shfl_xor_sync(0xffffffffu, s, o);
    float lse = logf(s) + mx;

    if (lane < 16)
        *reinterpret_cast<float4*>(out + (size_t)node * NCLASS + (cq << 2)) =
            make_float4(a.x - lse, a.y - lse, a.z - lse, a.w - lse);
}

// ---------------------------------------------------------------------------
extern "C" void kernel_launch(void* const* d_in, const int* in_sizes, int n_in,
                              void* d_out, int out_size)
{
    const float* x    = (const float*)d_in[0];
    const int*   edge = (const int*)  d_in[1];
    const float* W1   = (const float*)d_in[2];
    const float* W2   = (const float*)d_in[3];
    float* out = (float*)d_out;

    float *gX, *gH, *gT, *gW1t, *gW2t;
    unsigned *gK;
    cudaGetSymbolAddress((void**)&gX,   g_X);
    cudaGetSymbolAddress((void**)&gH,   g_H);
    cudaGetSymbolAddress((void**)&gT,   g_T);
    cudaGetSymbolAddress((void**)&gK,   g_keep);
    cudaGetSymbolAddress((void**)&gW1t, g_W1t);
    cudaGetSymbolAddress((void**)&gW2t, g_W2t);

    constexpr int SMEM1 = 2 * (2 * 128 + 2 * 128) * 20 * 4;   // 81920
    constexpr int SMEM2 = 2 * (2 * 64 + 2 * 64) * 20 * 4;     // 40960
    cudaFuncSetAttribute(agg1_kernel,
                         cudaFuncAttributeMaxDynamicSharedMemorySize, A1_SMEM_B);
    cudaFuncSetAttribute(gemm_bf16<128, 128, 128, 64, 32, true>,
                         cudaFuncAttributeMaxDynamicSharedMemorySize, SMEM1);
    cudaFuncSetAttribute(gemm_bf16<64, 64, 256, 32, 16, false>,
                         cudaFuncAttributeMaxDynamicSharedMemorySize, SMEM2);

    // K1: gX = adj @ x (smem-staged, branchless) + keep masks + W transposes
    agg1_kernel<<<176, 256, A1_SMEM_B>>>(x, edge, W1, W2, gX, gK, gW1t, gW2t);
    // K2: gH = relu(gX @ W1)
    gemm_bf16<128, 128, 128, 64, 32, true>
        <<<dim3(64, 2), 256, SMEM1>>>(gX, gW1t, gH, NHID);
    // K3: gT = gH @ W2
    gemm_bf16<64, 64, 256, 32, 16, false>
        <<<dim3(128, 1), 256, SMEM2>>>(gH, gW2t, gT, NCLASS);
    // K4: out = log_softmax(adj @ gT)  (branchless gather)
    agg_lsm_kernel<<<NN / 8, 256>>>(gT, edge, gK, out);
}